// round 13
// baseline (speedup 1.0000x reference)
#include <cuda_runtime.h>
#include <cuda_fp16.h>
#include <stdint.h>

// ---------------- device globals ----------------
__device__ __align__(16) uint32_t g_wt[72 * 2048];        // [kk*8+cb][n=64][k=64] fp16 swizzled
__device__ __align__(16) uint32_t g_wh[8 * 1536];         // [cb][n=48][k=64] fp16 swizzled
__device__ __align__(16) uint32_t g_feat[2048u * 128 * 256]; // [tile][pos][256 u32 = 512 fp16 ch]

__device__ __forceinline__ uint32_t pkh2(__half a, __half b) {
    return (uint32_t)__half_as_ushort(a) | ((uint32_t)__half_as_ushort(b) << 16);
}

// ---------------- prep: round+swizzle weights (coalesced reads) ----------------
__global__ void prep_kernel(const float* __restrict__ wb,
                            const float* __restrict__ wc, const float* __restrict__ wr) {
    int gid = blockIdx.x * 256 + threadIdx.x;
    if (gid < 147456) {
        int t = gid >> 11, idx = gid & 2047;
        int kk = t >> 3, cb = t & 7;
        int n = idx & 63, kw = idx >> 6;           // n fastest -> coalesced LDG
        int k = kw * 2;
        const float* ws = wb + ((size_t)kk * 64 + k) * 512 + cb * 64 + n;
        uint32_t sidx = (uint32_t)n * 32 + ((((uint32_t)kw >> 2) ^ (n & 7)) << 2) + (kw & 3);
        g_wt[t * 2048 + sidx] = pkh2(__float2half_rn(ws[0]), __float2half_rn(ws[512]));
    } else if (gid < 147456 + 12288) {
        int e = gid - 147456;
        int cb = e / 1536, idx = e - cb * 1536;
        int n = idx % 48, kw = idx / 48;           // n fastest
        int k = kw * 2;
        int c0 = cb * 64 + k;
        float f0 = 0.f, f1 = 0.f;
        if (n < 9)       { f0 = wc[c0 * 9 + n];      f1 = wc[(c0 + 1) * 9 + n]; }
        else if (n < 45) { f0 = wr[c0 * 36 + n - 9]; f1 = wr[(c0 + 1) * 36 + n - 9]; }
        uint32_t sidx = (uint32_t)n * 32 + ((((uint32_t)kw >> 2) ^ (n & 7)) << 2) + (kw & 3);
        g_wh[cb * 1536 + sidx] = pkh2(__float2half_rn(f0), __float2half_rn(f1));
    }
}

// ---------------- warp-MMA plumbing ----------------
__device__ __forceinline__ uint32_t smem_u32(const void* p) {
    uint32_t a;
    asm("{ .reg .u64 t; cvta.to.shared.u64 t, %1; cvt.u32.u64 %0, t; }" : "=r"(a) : "l"(p));
    return a;
}
__device__ __forceinline__ void ldsm4(uint32_t* r, uint32_t addr) {
    asm volatile("ldmatrix.sync.aligned.m8n8.x4.shared.b16 {%0,%1,%2,%3}, [%4];"
                 : "=r"(r[0]), "=r"(r[1]), "=r"(r[2]), "=r"(r[3]) : "r"(addr));
}
__device__ __forceinline__ void mma16816(float* d, const uint32_t* a, uint32_t b0, uint32_t b1) {
    asm volatile("mma.sync.aligned.m16n8k16.row.col.f32.f16.f16.f32 "
                 "{%0,%1,%2,%3}, {%4,%5,%6,%7}, {%8,%9}, {%0,%1,%2,%3};"
                 : "+f"(d[0]), "+f"(d[1]), "+f"(d[2]), "+f"(d[3])
                 : "r"(a[0]), "r"(a[1]), "r"(a[2]), "r"(a[3]), "r"(b0), "r"(b1));
}
#define CP16(dst, src) asm volatile("cp.async.cg.shared.global [%0], [%1], 16;" :: "r"(dst), "l"(src) : "memory")
#define CP_COMMIT()    asm volatile("cp.async.commit_group;" ::: "memory")
#define CP_WAITG(n)    asm volatile("cp.async.wait_group %0;" :: "n"(n) : "memory")

__device__ __forceinline__ uint32_t pkf(float v0, float v1) {   // low16 = v0 (fp16, rn)
    uint32_t r;
    asm("cvt.rn.f16x2.f32 %0, %1, %2;" : "=r"(r) : "f"(v1), "f"(v0));
    return r;
}
__device__ __forceinline__ uint32_t hmax2z(uint32_t v) {        // packed relu
    uint32_t r;
    asm("max.f16x2 %0, %1, %2;" : "=r"(r) : "r"(v), "r"(0u));
    return r;
}

// ================= kernel 1: trunk — 16x16 tile/CTA, M=64 per warp, occ 2 =================
#define SM1_WHI  0            // 324 rows x 128B = 41472
#define SM1_B    41472        // 3 stages x 8192 = 24576
#define SM1_BIAS 66048        // 512 floats = 2048
#define SMEM1    68096

__global__ __launch_bounds__(128, 2)
void rpn_trunk_kernel(const float* __restrict__ x, const float* __restrict__ b_base)
{
    extern __shared__ unsigned char smem[];
    const uint32_t sb = smem_u32(smem);
    const int tid = threadIdx.x, wid = tid >> 5, lane = tid & 31;
    const int bid = blockIdx.x;               // 1024 = b(4) x TY(16) x tx(16)
    const int b  = bid >> 8;
    const int TY = (bid >> 4) & 15;
    const int tx = bid & 15;
    const int gy0 = TY * 16, gx0 = tx * 16;

    // prologue B prefetch (taps 0,1 -> stages 0,1)
    {
        const uint4* s0 = (const uint4*)(g_wt);
        #pragma unroll
        for (int i = 0; i < 4; i++)
            CP16(sb + SM1_B + 0 * 8192 + (tid + 128 * i) * 16, s0 + tid + 128 * i);
        CP_COMMIT();
        const uint4* s1 = (const uint4*)(g_wt + 8 * 2048);
        #pragma unroll
        for (int i = 0; i < 4; i++)
            CP16(sb + SM1_B + 1 * 8192 + (tid + 128 * i) * 16, s1 + tid + 128 * i);
        CP_COMMIT();
    }

    // input window 18x18x64: LDG f32 -> fp16, chunk-xor swizzled (324 rows x 128B)
    const float* xb = x + (size_t)b * 256 * 256 * 64;
    uint32_t* whi = (uint32_t*)(smem + SM1_WHI);
    for (int e = tid; e < 5184; e += 128) {
        int r = e >> 4, c4 = e & 15;
        int wy = r / 18, wx = r - wy * 18;
        int gy = gy0 - 1 + wy, gx = gx0 - 1 + wx;
        float4 v = make_float4(0.f, 0.f, 0.f, 0.f);
        if ((unsigned)gy < 256u && (unsigned)gx < 256u)
            v = *(const float4*)(xb + (size_t)(gy * 256 + gx) * 64 + c4 * 4);
        uint32_t p0 = pkf(v.x, v.y);
        uint32_t p1 = pkf(v.z, v.w);
        int c8 = c4 >> 1;
        uint32_t di = (uint32_t)r * 32 + (uint32_t)((c8 ^ (r & 7)) << 2) + (uint32_t)(c4 & 1) * 2;
        *(uint2*)(whi + di) = make_uint2(p0, p1);
    }
    {
        float* sbias = (float*)(smem + SM1_BIAS);
        #pragma unroll
        for (int i = 0; i < 4; i++) sbias[tid + 128 * i] = b_base[tid + 128 * i];
    }
    __syncthreads();

    const int rowA  = ((lane >> 3) & 1) * 8 + (lane & 7);
    const int kc    = lane >> 4;
    const int g     = lane >> 2, tg = lane & 3;
    const uint32_t rowAx128 = (uint32_t)rowA * 128;
    const int rA7 = rowA & 7;

    #pragma unroll 1
    for (int cb = 0; cb < 8; cb++) {
        float acc[4][8][4];
        {
            const float* sbias = (const float*)(smem + SM1_BIAS) + cb * 64 + 2 * tg;
            #pragma unroll
            for (int j = 0; j < 8; j++) {
                float v0 = sbias[8 * j], v1 = sbias[8 * j + 1];
                #pragma unroll
                for (int mf = 0; mf < 4; mf++) {
                    acc[mf][j][0] = v0; acc[mf][j][1] = v1;
                    acc[mf][j][2] = v0; acc[mf][j][3] = v1;
                }
            }
        }

        #pragma unroll 1
        for (int kk = 0; kk < 9; kk++) {
            const int T = cb * 9 + kk;

            CP_WAITG(1);            // group T (issued at T-2) complete
            __syncthreads();

            {   // prefetch tap T+2 into stage (T+2)%3 (unconditional commit keeps count)
                const int T2 = T + 2;
                if (T2 < 72) {
                    const int cbp = T2 / 9, kkp = T2 - 9 * cbp;
                    const uint4* s2 = (const uint4*)(g_wt + (size_t)(kkp * 8 + cbp) * 2048);
                    uint32_t dst = sb + SM1_B + (uint32_t)(T2 % 3) * 8192;
                    #pragma unroll
                    for (int i = 0; i < 4; i++)
                        CP16(dst + (tid + 128 * i) * 16, s2 + tid + 128 * i);
                }
                CP_COMMIT();
            }

            const int ky = kk / 3, kx = kk - 3 * ky;
            const uint32_t sB = sb + SM1_B + (uint32_t)(T % 3) * 8192;

            #pragma unroll
            for (int ks = 0; ks < 4; ks++) {
                const uint32_t xoff = (uint32_t)(((ks * 2 + kc) ^ rA7) << 4);
                uint32_t ah[4][4];
                #pragma unroll
                for (int mf = 0; mf < 4; mf++) {
                    int r = (wid * 4 + mf + ky) * 18 + rowA + kx;   // y = 4*wid+mf
                    uint32_t off = (uint32_t)r * 128 + (uint32_t)(((ks * 2 + kc) ^ (r & 7)) << 4);
                    ldsm4(ah[mf], sb + SM1_WHI + off);
                }
                uint32_t bA[4], bB[4];
                ldsm4(bA, sB + 0 * 2048 + rowAx128 + xoff);
                ldsm4(bB, sB + 1 * 2048 + rowAx128 + xoff);
                #pragma unroll
                for (int mf = 0; mf < 4; mf++) {
                    mma16816(acc[mf][0], ah[mf], bA[0], bA[2]);
                    mma16816(acc[mf][1], ah[mf], bA[1], bA[3]);
                }
                ldsm4(bA, sB + 2 * 2048 + rowAx128 + xoff);
                #pragma unroll
                for (int mf = 0; mf < 4; mf++) {
                    mma16816(acc[mf][2], ah[mf], bB[0], bB[2]);
                    mma16816(acc[mf][3], ah[mf], bB[1], bB[3]);
                }
                ldsm4(bB, sB + 3 * 2048 + rowAx128 + xoff);
                #pragma unroll
                for (int mf = 0; mf < 4; mf++) {
                    mma16816(acc[mf][4], ah[mf], bA[0], bA[2]);
                    mma16816(acc[mf][5], ah[mf], bA[1], bA[3]);
                }
                #pragma unroll
                for (int mf = 0; mf < 4; mf++) {
                    mma16816(acc[mf][6], ah[mf], bB[0], bB[2]);
                    mma16816(acc[mf][7], ah[mf], bB[1], bB[3]);
                }
            }
        }

        // feat = relu(acc) fp16 -> g_feat in R12's exact [tile2048][pos128][256] layout
        #pragma unroll
        for (int mf = 0; mf < 4; mf++) {
            int y = 4 * wid + mf;                          // 0..15 within CTA
            uint32_t tile = (uint32_t)b * 512 + (uint32_t)(2 * TY + (y >> 3)) * 16 + (uint32_t)tx;
            uint32_t base = (tile * 128 + (uint32_t)((y & 7) * 16 + g)) * 256
                          + (uint32_t)cb * 32 + (uint32_t)tg;
            #pragma unroll
            for (int j = 0; j < 8; j++) {
                uint32_t lo = hmax2z(pkf(acc[mf][j][0], acc[mf][j][1]));   // x = g
                uint32_t hi = hmax2z(pkf(acc[mf][j][2], acc[mf][j][3]));   // x = g+8
                g_feat[base + (uint32_t)j * 4]        = lo;
                g_feat[base + 2048 + (uint32_t)j * 4] = hi;
            }
        }
    }
}

// ================= kernel 2: head (verbatim from R12 — proven bit-exact) =================
#define SM2_A   0            // 2 stages x 16384 (feat tile 128 pos x 64 ch fp16, swizzled)
#define SM2_W   32768        // 2 stages x 6144
#define SMEM2   45056

__global__ __launch_bounds__(128, 4)
void rpn_head_kernel(const float* __restrict__ b_cls, const float* __restrict__ b_reg,
                     float* __restrict__ out)
{
    extern __shared__ unsigned char smem[];
    const uint32_t sb = smem_u32(smem);
    const int tid = threadIdx.x, wid = tid >> 5, lane = tid & 31;
    const int bid = blockIdx.x;
    const int b = bid >> 9;
    const int tno = bid & 511;
    const int gy0 = (tno >> 4) * 8, gx0 = (tno & 15) * 16;

    const int rowA  = ((lane >> 3) & 1) * 8 + (lane & 7);
    const int kc    = lane >> 4;
    const int g     = lane >> 2, tg = lane & 3;
    const uint32_t rowAx128 = (uint32_t)rowA * 128;
    const int rA7 = rowA & 7;

    // prologue: stage cb=0 (feat + wh)
    {
        #pragma unroll
        for (int i = 0; i < 8; i++) {
            int e = tid + 128 * i;
            int pos = e >> 3, c8 = e & 7;
            const uint4* src = (const uint4*)g_feat + ((size_t)bid * 128 + pos) * 64 + c8;
            CP16(sb + SM2_A + (uint32_t)pos * 128 + (uint32_t)((c8 ^ (pos & 7)) << 4), src);
        }
        const uint4* s1 = (const uint4*)(g_wh);
        #pragma unroll
        for (int i = 0; i < 3; i++)
            CP16(sb + SM2_W + (tid + 128 * i) * 16, s1 + tid + 128 * i);
        CP_COMMIT();
    }

    float hacc[2][6][4];
    #pragma unroll
    for (int mt = 0; mt < 2; mt++)
        #pragma unroll
        for (int nt = 0; nt < 6; nt++)
            #pragma unroll
            for (int q = 0; q < 4; q++) hacc[mt][nt][q] = 0.f;

    #pragma unroll 1
    for (int cb = 0; cb < 8; cb++) {
        __syncthreads();
        if (cb < 7) {
            const int c2 = cb + 1;
            #pragma unroll
            for (int i = 0; i < 8; i++) {
                int e = tid + 128 * i;
                int pos = e >> 3, c8 = e & 7;
                const uint4* src = (const uint4*)g_feat + ((size_t)bid * 128 + pos) * 64 + c2 * 8 + c8;
                CP16(sb + SM2_A + (uint32_t)(c2 & 1) * 16384 +
                     (uint32_t)pos * 128 + (uint32_t)((c8 ^ (pos & 7)) << 4), src);
            }
            const uint4* s1 = (const uint4*)(g_wh + c2 * 1536);
            #pragma unroll
            for (int i = 0; i < 3; i++)
                CP16(sb + SM2_W + (uint32_t)(c2 & 1) * 6144 + (tid + 128 * i) * 16, s1 + tid + 128 * i);
        }
        CP_COMMIT();
        CP_WAITG(1);
        __syncthreads();

        const uint32_t stageA = sb + SM2_A + (uint32_t)(cb & 1) * 16384;
        const uint32_t stageW = sb + SM2_W + (uint32_t)(cb & 1) * 6144;

        #pragma unroll
        for (int hk = 0; hk < 4; hk++) {
            const uint32_t xoff = (uint32_t)(((hk * 2 + kc) ^ rA7) << 4);
            uint32_t ah[2][4];
            #pragma unroll
            for (int mt = 0; mt < 2; mt++) {
                int r = wid * 32 + mt * 16 + rowA;
                ldsm4(ah[mt], stageA + (uint32_t)r * 128 + (uint32_t)(((hk * 2 + kc) ^ (r & 7)) << 4));
            }
            #pragma unroll
            for (int np = 0; np < 3; np++) {
                uint32_t bh[4];
                ldsm4(bh, stageW + (uint32_t)(np * 2048) + rowAx128 + xoff);
                #pragma unroll
                for (int mt = 0; mt < 2; mt++) {
                    mma16816(hacc[mt][2 * np],     ah[mt], bh[0], bh[2]);
                    mma16816(hacc[mt][2 * np + 1], ah[mt], bh[1], bh[3]);
                }
            }
        }
    }

    // epilogue
    __syncthreads();
    float* feat = (float*)smem;   // [128][48]
    #pragma unroll
    for (int mt = 0; mt < 2; mt++) {
        int p0 = wid * 32 + mt * 16 + g;
        #pragma unroll
        for (int nt = 0; nt < 6; nt++) {
            int c = 8 * nt + 2 * tg;
            feat[p0 * 48 + c]           = hacc[mt][nt][0];
            feat[p0 * 48 + c + 1]       = hacc[mt][nt][1];
            feat[(p0 + 8) * 48 + c]     = hacc[mt][nt][2];
            feat[(p0 + 8) * 48 + c + 1] = hacc[mt][nt][3];
        }
    }
    __syncthreads();
    {
        int y = gy0 + (tid >> 4), xo = gx0 + (tid & 15);
        float* o = out + (((size_t)b * 256 + y) * 256 + xo) * 45;
        const float* f = feat + tid * 48;
        float sc[9];
        #pragma unroll
        for (int j = 0; j < 9; j++) {
            float z = f[j] + __ldg(b_cls + j);
            sc[j] = 1.f / (1.f + __expf(-z));
            o[j] = sc[j];
        }
        #pragma unroll
        for (int an = 0; an < 9; an++) {
            float msk = sc[an] > 0.7f ? 1.f : 0.f;
            #pragma unroll
            for (int i = 0; i < 4; i++)
                o[9 + an * 4 + i] = (f[9 + an * 4 + i] + __ldg(b_reg + an * 4 + i)) * msk;
        }
    }
}

extern "C" void kernel_launch(void* const* d_in, const int* in_sizes, int n_in,
                              void* d_out, int out_size)
{
    const float* x      = (const float*)d_in[0];
    const float* w_base = (const float*)d_in[1];
    const float* b_base = (const float*)d_in[2];
    const float* w_cls  = (const float*)d_in[3];
    const float* b_cls  = (const float*)d_in[4];
    const float* w_reg  = (const float*)d_in[5];
    const float* b_reg  = (const float*)d_in[6];

    cudaFuncSetAttribute(rpn_trunk_kernel,
                         cudaFuncAttributeMaxDynamicSharedMemorySize, SMEM1);
    cudaFuncSetAttribute(rpn_head_kernel,
                         cudaFuncAttributeMaxDynamicSharedMemorySize, SMEM2);

    prep_kernel<<<624, 256>>>(w_base, w_cls, w_reg);
    rpn_trunk_kernel<<<1024, 128, SMEM1>>>(x, b_base);
    rpn_head_kernel<<<2048, 128, SMEM2>>>(b_cls, b_reg, (float*)d_out);
}

// round 14
// speedup vs baseline: 1.2064x; 1.2064x over previous
#include <cuda_runtime.h>
#include <cuda_fp16.h>
#include <stdint.h>

// ---------------- device globals (pre-converted weights) ----------------
__device__ __align__(16) uint32_t g_wt[72 * 2048];  // [kk*8+cb]: [n=64][k=64] fp16 swizzled
__device__ __align__(16) uint32_t g_wh[8 * 1536];   // [cb]: [n=48][k=64] fp16 swizzled

__device__ __forceinline__ uint32_t pkh2(__half a, __half b) {
    return (uint32_t)__half_as_ushort(a) | ((uint32_t)__half_as_ushort(b) << 16);
}

// ---------------- prep: round+swizzle weights (coalesced: n fastest) ----------------
__global__ void prep_kernel(const float* __restrict__ wb,
                            const float* __restrict__ wc, const float* __restrict__ wr) {
    int gid = blockIdx.x * 256 + threadIdx.x;
    if (gid < 147456) {
        int t = gid >> 11, idx = gid & 2047;
        int kk = t >> 3, cb = t & 7;
        int n = idx & 63, kw = idx >> 6;           // n fastest -> coalesced LDG
        int k = kw * 2;
        const float* ws = wb + ((size_t)kk * 64 + k) * 512 + cb * 64 + n;
        uint32_t sidx = (uint32_t)n * 32 + ((((uint32_t)kw >> 2) ^ (n & 7)) << 2) + (kw & 3);
        g_wt[t * 2048 + sidx] = pkh2(__float2half_rn(ws[0]), __float2half_rn(ws[512]));
    } else if (gid < 147456 + 12288) {
        int e = gid - 147456;
        int cb = e / 1536, idx = e - cb * 1536;
        int n = idx % 48, kw = idx / 48;           // n fastest
        int k = kw * 2;
        int c0 = cb * 64 + k;
        float f0 = 0.f, f1 = 0.f;
        if (n < 9)       { f0 = wc[c0 * 9 + n];      f1 = wc[(c0 + 1) * 9 + n]; }
        else if (n < 45) { f0 = wr[c0 * 36 + n - 9]; f1 = wr[(c0 + 1) * 36 + n - 9]; }
        uint32_t sidx = (uint32_t)n * 32 + ((((uint32_t)kw >> 2) ^ (n & 7)) << 2) + (kw & 3);
        g_wh[cb * 1536 + sidx] = pkh2(__float2half_rn(f0), __float2half_rn(f1));
    }
}

// ---------------- warp-MMA plumbing ----------------
__device__ __forceinline__ uint32_t smem_u32(const void* p) {
    uint32_t a;
    asm("{ .reg .u64 t; cvta.to.shared.u64 t, %1; cvt.u32.u64 %0, t; }" : "=r"(a) : "l"(p));
    return a;
}
__device__ __forceinline__ void ldsm4(uint32_t* r, uint32_t addr) {
    asm volatile("ldmatrix.sync.aligned.m8n8.x4.shared.b16 {%0,%1,%2,%3}, [%4];"
                 : "=r"(r[0]), "=r"(r[1]), "=r"(r[2]), "=r"(r[3]) : "r"(addr));
}
__device__ __forceinline__ void mma16816(float* d, const uint32_t* a, uint32_t b0, uint32_t b1) {
    asm volatile("mma.sync.aligned.m16n8k16.row.col.f32.f16.f16.f32 "
                 "{%0,%1,%2,%3}, {%4,%5,%6,%7}, {%8,%9}, {%0,%1,%2,%3};"
                 : "+f"(d[0]), "+f"(d[1]), "+f"(d[2]), "+f"(d[3])
                 : "r"(a[0]), "r"(a[1]), "r"(a[2]), "r"(a[3]), "r"(b0), "r"(b1));
}
#define CP16(dst, src) asm volatile("cp.async.cg.shared.global [%0], [%1], 16;" :: "r"(dst), "l"(src) : "memory")
#define CP_COMMIT()    asm volatile("cp.async.commit_group;" ::: "memory")
#define CP_WAITG(n)    asm volatile("cp.async.wait_group %0;" :: "n"(n) : "memory")

__device__ __forceinline__ uint32_t pkf(float v0, float v1) {   // low16 = v0 (fp16, rn)
    uint32_t r;
    asm("cvt.rn.f16x2.f32 %0, %1, %2;" : "=r"(r) : "f"(v1), "f"(v0));
    return r;
}
__device__ __forceinline__ uint32_t hmax2z(uint32_t v) {        // packed relu
    uint32_t r;
    asm("max.f16x2 %0, %1, %2;" : "=r"(r) : "r"(v), "r"(0u));
    return r;
}

// ---------------- SMEM layout (R11/R9 swizzled layout) ----------------
#define SM_WHI  0            // 180 rows x 128B = 23040
#define SM_B    23040        // 4 stages x 8192 = 32768
#define SM_HB   55808        // 6144
#define SM_BIAS 61952        // 512 floats = 2048
#define SMEM_BYTES 64000

__global__ __launch_bounds__(128, 3)
void rpn_mma_kernel(const float* __restrict__ x,
                    const float* __restrict__ b_base, const float* __restrict__ b_cls,
                    const float* __restrict__ b_reg, float* __restrict__ out)
{
    extern __shared__ unsigned char smem[];
    const uint32_t sb = smem_u32(smem);
    const int tid = threadIdx.x, wid = tid >> 5, lane = tid & 31;
    const int bid = blockIdx.x;
    const int b = bid >> 9;
    const int tno = bid & 511;
    const int gy0 = (tno >> 4) * 8, gx0 = (tno & 15) * 16;

    // prologue B prefetch first (overlaps window LDG + cvt)
    {
        const uint4* s0 = (const uint4*)(g_wt + 0 * 2048);     // kk=0,cb=0
        #pragma unroll
        for (int i = 0; i < 4; i++)
            CP16(sb + SM_B + 0 * 8192 + (tid + 128 * i) * 16, s0 + tid + 128 * i);
        CP_COMMIT();
        const uint4* s1 = (const uint4*)(g_wt + 8 * 2048);     // kk=1,cb=0
        #pragma unroll
        for (int i = 0; i < 4; i++)
            CP16(sb + SM_B + 1 * 8192 + (tid + 128 * i) * 16, s1 + tid + 128 * i);
        CP_COMMIT();
    }

    // ---- input window 10x18x64: LDG f32 -> fp16 in-kernel, chunk-xor swizzled ----
    const float* xb = x + (size_t)b * 256 * 256 * 64;
    uint32_t* whi = (uint32_t*)(smem + SM_WHI);
    for (int e = tid; e < 2880; e += 128) {
        int r = e >> 4, c4 = e & 15;
        int wy = r / 18, wx = r - wy * 18;
        int gy = gy0 - 1 + wy, gx = gx0 - 1 + wx;
        float4 v = make_float4(0.f, 0.f, 0.f, 0.f);
        if ((unsigned)gy < 256u && (unsigned)gx < 256u)
            v = *(const float4*)(xb + (size_t)(gy * 256 + gx) * 64 + c4 * 4);
        uint32_t p0 = pkf(v.x, v.y);
        uint32_t p1 = pkf(v.z, v.w);
        int c8 = c4 >> 1;
        uint32_t di = (uint32_t)r * 32 + (uint32_t)((c8 ^ (r & 7)) << 2) + (uint32_t)(c4 & 1) * 2;
        *(uint2*)(whi + di) = make_uint2(p0, p1);
    }
    // full bias table once
    {
        float* sbias = (float*)(smem + SM_BIAS);
        #pragma unroll
        for (int i = 0; i < 4; i++) sbias[tid + 128 * i] = b_base[tid + 128 * i];
    }
    __syncthreads();

    // per-lane ldmatrix invariants
    const int rowA  = ((lane >> 3) & 1) * 8 + (lane & 7);
    const int kc    = lane >> 4;
    const int g     = lane >> 2, tg = lane & 3;
    const uint32_t rowAx128 = (uint32_t)rowA * 128;
    const int rA7 = rowA & 7;

    float hacc[2][6][4];
    #pragma unroll
    for (int mt = 0; mt < 2; mt++)
        #pragma unroll
        for (int nt = 0; nt < 6; nt++)
            #pragma unroll
            for (int q = 0; q < 4; q++) hacc[mt][nt][q] = 0.f;

    #pragma unroll 1
    for (int cb = 0; cb < 8; cb++) {
        // acc init = bias (folds head bias-add away; mathematically exact)
        float acc[2][8][4];
        {
            const float* sbias = (const float*)(smem + SM_BIAS) + cb * 64 + 2 * tg;
            #pragma unroll
            for (int j = 0; j < 8; j++) {
                float v0 = sbias[8 * j], v1 = sbias[8 * j + 1];
                #pragma unroll
                for (int mt = 0; mt < 2; mt++) {
                    acc[mt][j][0] = v0; acc[mt][j][1] = v1;
                    acc[mt][j][2] = v0; acc[mt][j][3] = v1;
                }
            }
        }

        #pragma unroll 1
        for (int kk = 0; kk < 9; kk++) {
            const int T = cb * 9 + kk;

            if ((T & 1) == 0) {      // interval boundary: one wait+barrier per 2 taps
                CP_WAITG(0);
                __syncthreads();

                #pragma unroll
                for (int d = 2; d <= 3; d++) {
                    const int T2 = T + d;
                    if (T2 < 72) {
                        const int cbp = T2 / 9, kkp = T2 - 9 * cbp;
                        const uint4* s2 = (const uint4*)(g_wt + (size_t)(kkp * 8 + cbp) * 2048);
                        uint32_t dst = sb + SM_B + (uint32_t)(T2 & 3) * 8192;
                        #pragma unroll
                        for (int i = 0; i < 4; i++)
                            CP16(dst + (tid + 128 * i) * 16, s2 + tid + 128 * i);
                    }
                }
                if (kk == 5 || kk == 6) {
                    const uint4* s1 = (const uint4*)(g_wh + cb * 1536);
                    #pragma unroll
                    for (int i = 0; i < 3; i++)
                        CP16(sb + SM_HB + (tid + 128 * i) * 16, s1 + tid + 128 * i);
                }
                CP_COMMIT();
            }

            // ---- compute tap T ----
            const int ky = kk / 3, kx = kk - 3 * ky;
            const uint32_t sB = sb + SM_B + (uint32_t)(T & 3) * 8192;

            #pragma unroll
            for (int ks = 0; ks < 4; ks++) {
                const uint32_t xoff = (uint32_t)(((ks * 2 + kc) ^ rA7) << 4);
                uint32_t ah[2][4];
                #pragma unroll
                for (int mt = 0; mt < 2; mt++) {
                    int r = (wid * 2 + mt + ky) * 18 + rowA + kx;
                    uint32_t off = (uint32_t)r * 128 + (uint32_t)(((ks * 2 + kc) ^ (r & 7)) << 4);
                    ldsm4(ah[mt], sb + SM_WHI + off);
                }
                // B double-buffered across np (ldsm for np+1 ahead of np's MMAs)
                uint32_t bA[4], bB[4];
                ldsm4(bA, sB + 0 * 2048 + rowAx128 + xoff);
                ldsm4(bB, sB + 1 * 2048 + rowAx128 + xoff);
                #pragma unroll
                for (int mt = 0; mt < 2; mt++) {
                    mma16816(acc[mt][0], ah[mt], bA[0], bA[2]);
                    mma16816(acc[mt][1], ah[mt], bA[1], bA[3]);
                }
                ldsm4(bA, sB + 2 * 2048 + rowAx128 + xoff);
                #pragma unroll
                for (int mt = 0; mt < 2; mt++) {
                    mma16816(acc[mt][2], ah[mt], bB[0], bB[2]);
                    mma16816(acc[mt][3], ah[mt], bB[1], bB[3]);
                }
                ldsm4(bB, sB + 3 * 2048 + rowAx128 + xoff);
                #pragma unroll
                for (int mt = 0; mt < 2; mt++) {
                    mma16816(acc[mt][4], ah[mt], bA[0], bA[2]);
                    mma16816(acc[mt][5], ah[mt], bA[1], bA[3]);
                }
                #pragma unroll
                for (int mt = 0; mt < 2; mt++) {
                    mma16816(acc[mt][6], ah[mt], bB[0], bB[2]);
                    mma16816(acc[mt][7], ah[mt], bB[1], bB[3]);
                }
            }
        }

        // ---- head: single-term; B ldsm issued BEFORE cvt chain so LDS hides under it ----
        #pragma unroll
        for (int hk = 0; hk < 4; hk++) {
            const uint32_t xoff = (uint32_t)(((hk * 2 + kc) ^ rA7) << 4);
            uint32_t bh[3][4];
            #pragma unroll
            for (int np = 0; np < 3; np++)
                ldsm4(bh[np], sb + SM_HB + (uint32_t)(np * 2048) + rowAx128 + xoff);
            uint32_t hA[2][4];
            #pragma unroll
            for (int mt = 0; mt < 2; mt++) {
                #pragma unroll
                for (int q = 0; q < 4; q++) {
                    int j  = 2 * hk + (q >> 1);
                    int d0 = (q & 1) * 2;
                    hA[mt][q] = hmax2z(pkf(acc[mt][j][d0], acc[mt][j][d0 + 1]));
                }
            }
            #pragma unroll
            for (int np = 0; np < 3; np++) {
                #pragma unroll
                for (int mt = 0; mt < 2; mt++) {
                    mma16816(hacc[mt][2 * np],     hA[mt], bh[np][0], bh[np][2]);
                    mma16816(hacc[mt][2 * np + 1], hA[mt], bh[np][1], bh[np][3]);
                }
            }
        }
    }

    // ---- epilogue: stage head results, then per-position sigmoid/mask ----
    __syncthreads();
    float* feat = (float*)smem;   // [128][48] (B stages dead now)
    #pragma unroll
    for (int mt = 0; mt < 2; mt++) {
        int p0 = wid * 32 + mt * 16 + g;
        #pragma unroll
        for (int nt = 0; nt < 6; nt++) {
            int c = 8 * nt + 2 * tg;
            feat[p0 * 48 + c]           = hacc[mt][nt][0];
            feat[p0 * 48 + c + 1]       = hacc[mt][nt][1];
            feat[(p0 + 8) * 48 + c]     = hacc[mt][nt][2];
            feat[(p0 + 8) * 48 + c + 1] = hacc[mt][nt][3];
        }
    }
    __syncthreads();
    {
        int y = gy0 + (tid >> 4), xo = gx0 + (tid & 15);
        float* o = out + (((size_t)b * 256 + y) * 256 + xo) * 45;
        const float* f = feat + tid * 48;
        float sc[9];
        #pragma unroll
        for (int j = 0; j < 9; j++) {
            float z = f[j] + __ldg(b_cls + j);
            sc[j] = 1.f / (1.f + __expf(-z));
            o[j] = sc[j];
        }
        #pragma unroll
        for (int an = 0; an < 9; an++) {
            float msk = sc[an] > 0.7f ? 1.f : 0.f;
            #pragma unroll
            for (int i = 0; i < 4; i++)
                o[9 + an * 4 + i] = (f[9 + an * 4 + i] + __ldg(b_reg + an * 4 + i)) * msk;
        }
    }
}

extern "C" void kernel_launch(void* const* d_in, const int* in_sizes, int n_in,
                              void* d_out, int out_size)
{
    const float* x      = (const float*)d_in[0];
    const float* w_base = (const float*)d_in[1];
    const float* b_base = (const float*)d_in[2];
    const float* w_cls  = (const float*)d_in[3];
    const float* b_cls  = (const float*)d_in[4];
    const float* w_reg  = (const float*)d_in[5];
    const float* b_reg  = (const float*)d_in[6];

    cudaFuncSetAttribute(rpn_mma_kernel,
                         cudaFuncAttributeMaxDynamicSharedMemorySize, SMEM_BYTES);

    prep_kernel<<<624, 256>>>(w_base, w_cls, w_reg);
    rpn_mma_kernel<<<2048, 128, SMEM_BYTES>>>(x, b_base, b_cls, b_reg, (float*)d_out);
}